// round 4
// baseline (speedup 1.0000x reference)
#include <cuda_runtime.h>

// GAT layer:  B=8, N=1024, F_IN=25, H=8, D=16
// out = [ relu(h_prime) : 8*1024*128 floats | alpha : 8*8*1024*1024 floats ]
//
// Math used (softmax row-shift cancellation):
//   e[i,j] = ei[i] + ej[j]  ->  alpha[i,j] = adj[i,j]*p[j] / S[i]
//   p[j]   = exp(ej[j] - max_j ej)          (per (b,h))
//   S[i]   = sum_j adj[i,j]*p[j]
//   h_prime[i,d] = (1/S[i]) * sum_j adj[i,j]*(p[j]*Wh[j,d])
// => one GEMM  C[1024 x 144] = A[1024 x 1024 (0/1)] @ Ycat[1024 x 144]
//    where Ycat cols 0..127 = p*Wh (h*16+d), cols 128..135 = p, 136..143 = 0.

#define BQ 8
#define NQ 1024
#define FQ 25
#define HQ 8
#define DQ 16
#define HD 128
#define NC 144

// scratch (zero-initialized at module load; cols 136..143 of Ycat stay 0 forever)
__device__ float g_Ycat[BQ * NQ * NC];   // [b][j][c]
__device__ float g_p[BQ * HQ * NQ];      // [b][h][j]
__device__ float g_invS[BQ * HQ * NQ];   // [b][h][i]

// ---------------- packed f32x2 helpers ----------------
__device__ __forceinline__ unsigned long long pack2(float lo, float hi) {
    unsigned long long r;
    asm("mov.b64 %0, {%1, %2};" : "=l"(r) : "f"(lo), "f"(hi));
    return r;
}
__device__ __forceinline__ void fma2(unsigned long long& d,
                                     unsigned long long a,
                                     unsigned long long b) {
    asm("fma.rn.f32x2 %0, %1, %2, %0;" : "+l"(d) : "l"(a), "l"(b));
}
__device__ __forceinline__ float2 unpack2(unsigned long long v) {
    float2 f;
    asm("mov.b64 {%0, %1}, %2;" : "=f"(f.x), "=f"(f.y) : "l"(v));
    return f;
}

// ---------------- K1: Wh, ej, blockmax, p, Ycat ----------------
// grid = B*H (64), 256 threads; each thread handles 4 nodes j.
__global__ __launch_bounds__(256) void k1_prep(const float* __restrict__ x,
                                               const float* __restrict__ W,
                                               const float* __restrict__ a) {
    int b = blockIdx.x >> 3;
    int h = blockIdx.x & 7;
    __shared__ float Ws[FQ * DQ];
    __shared__ float as[DQ];
    __shared__ float red[256];
    int tid = threadIdx.x;

    for (int i = tid; i < FQ * DQ; i += 256) Ws[i] = W[h * FQ * DQ + i];
    if (tid < DQ) as[tid] = a[h * 2 * DQ + DQ + tid];
    __syncthreads();

    float wh[4][DQ];
    float ej[4];
    float mx = -1e30f;
#pragma unroll
    for (int t = 0; t < 4; t++) {
        int j = tid + t * 256;
        const float* xr = x + (b * NQ + j) * FQ;
        float xf[FQ];
#pragma unroll
        for (int f = 0; f < FQ; f++) xf[f] = xr[f];
#pragma unroll
        for (int d = 0; d < DQ; d++) {
            float s = 0.f;
#pragma unroll
            for (int f = 0; f < FQ; f++) s += xf[f] * Ws[f * DQ + d];
            wh[t][d] = s;
        }
        float e = 0.f;
#pragma unroll
        for (int d = 0; d < DQ; d++) e += wh[t][d] * as[d];
        ej[t] = e;
        mx = fmaxf(mx, e);
    }
    red[tid] = mx;
    __syncthreads();
    for (int s = 128; s > 0; s >>= 1) {
        if (tid < s) red[tid] = fmaxf(red[tid], red[tid + s]);
        __syncthreads();
    }
    float M = red[0];

#pragma unroll
    for (int t = 0; t < 4; t++) {
        int j = tid + t * 256;
        float p = expf(ej[t] - M);
        float* yr = g_Ycat + (b * NQ + j) * NC;
#pragma unroll
        for (int d = 0; d < DQ; d++) yr[h * DQ + d] = wh[t][d] * p;
        yr[HD + h] = p;
        g_p[(b * HQ + h) * NQ + j] = p;
    }
}

// ---------------- K2: C = A @ Ycat  (+ epilogue: invS, relu(h')/S) --------
// grid = B * (N/64) = 128 blocks, 288 threads.
// thread (rg, cg): rg = tid/18 (16 row groups x 4 rows), cg = tid%18 (18 col
// groups x 8 cols). cg==16 -> S columns (128..135); cg==17 -> zero padding.
#define ADJ_LD 36  // padded row stride for adj tile (16B aligned, bank-shifted)

__global__ __launch_bounds__(288) void k2_gemm(const int* __restrict__ adj,
                                               float* __restrict__ out1) {
    int b  = blockIdx.x >> 4;
    int i0 = (blockIdx.x & 15) * 64;

    __shared__ __align__(16) float adjS[64 * ADJ_LD];
    __shared__ __align__(16) float Ys[32 * NC];
    __shared__ float Ssm[64 * 8];

    int tid = threadIdx.x;
    int rg = tid / 18, cg = tid % 18;
    int r0 = rg * 4, c0 = cg * 8;

    unsigned long long acc[4][4];
#pragma unroll
    for (int i = 0; i < 4; i++)
#pragma unroll
        for (int p = 0; p < 4; p++) acc[i][p] = 0ULL;

    for (int kt = 0; kt < 32; kt++) {
        int j0 = kt * 32;
        // adj tile: 64 rows x 32 ints = 512 int4 loads, convert to float
        for (int idx = tid; idx < 512; idx += 288) {
            int row = idx >> 3, c4 = idx & 7;
            int4 v = *(const int4*)(adj + ((size_t)(b * NQ + i0 + row)) * NQ + j0 + c4 * 4);
            float4 f = make_float4((float)v.x, (float)v.y, (float)v.z, (float)v.w);
            *(float4*)(adjS + row * ADJ_LD + c4 * 4) = f;
        }
        // Ycat tile: 32 rows x 144 cols = 1152 float4 loads
        for (int idx = tid; idx < 1152; idx += 288) {
            int row = idx / 36, c4 = idx % 36;
            *(float4*)(Ys + row * NC + c4 * 4) =
                *(const float4*)(g_Ycat + ((size_t)(b * NQ + j0 + row)) * NC + c4 * 4);
        }
        __syncthreads();

#pragma unroll 4
        for (int k = 0; k < 32; k++) {
            const ulonglong2* yp = (const ulonglong2*)(Ys + k * NC + c0);
            ulonglong2 u0 = yp[0];
            ulonglong2 u1 = yp[1];
#pragma unroll
            for (int i = 0; i < 4; i++) {
                float av = adjS[(r0 + i) * ADJ_LD + k];
                unsigned long long aa = pack2(av, av);
                fma2(acc[i][0], aa, u0.x);
                fma2(acc[i][1], aa, u0.y);
                fma2(acc[i][2], aa, u1.x);
                fma2(acc[i][3], aa, u1.y);
            }
        }
        __syncthreads();
    }

    // epilogue: S columns -> smem
    if (cg == 16) {
#pragma unroll
        for (int i = 0; i < 4; i++)
#pragma unroll
            for (int p = 0; p < 4; p++) {
                float2 f = unpack2(acc[i][p]);
                Ssm[(r0 + i) * 8 + 2 * p]     = f.x;
                Ssm[(r0 + i) * 8 + 2 * p + 1] = f.y;
            }
    }
    __syncthreads();

    if (cg == 16) {
#pragma unroll
        for (int i = 0; i < 4; i++)
#pragma unroll
            for (int hh = 0; hh < 8; hh++) {
                float s = Ssm[(r0 + i) * 8 + hh];
                g_invS[(b * HQ + hh) * NQ + i0 + r0 + i] = 1.0f / s;
            }
    }
    if (cg < 16) {
        int h = c0 >> 4;  // 8-aligned col group lies within one head block
#pragma unroll
        for (int i = 0; i < 4; i++) {
            float inv = 1.0f / Ssm[(r0 + i) * 8 + h];
            float o[8];
#pragma unroll
            for (int p = 0; p < 4; p++) {
                float2 f = unpack2(acc[i][p]);
                o[2 * p]     = fmaxf(f.x * inv, 0.f);
                o[2 * p + 1] = fmaxf(f.y * inv, 0.f);
            }
            float* op = out1 + ((size_t)(b * NQ + i0 + r0 + i)) * HD + c0;
            *(float4*)(op)     = make_float4(o[0], o[1], o[2], o[3]);
            *(float4*)(op + 4) = make_float4(o[4], o[5], o[6], o[7]);
        }
    }
}

// ---------------- K3: alpha writer ----------------
// grid = B*N (8192) blocks, 256 threads; one adj row per block, all 8 heads.
__global__ __launch_bounds__(256) void k3_alpha(const int* __restrict__ adj,
                                                float* __restrict__ alpha) {
    int b = blockIdx.x >> 10;
    int i = blockIdx.x & 1023;
    int tid = threadIdx.x;

    int4 a4 = *(const int4*)(adj + ((size_t)(b * NQ + i)) * NQ + tid * 4);

#pragma unroll
    for (int h = 0; h < HQ; h++) {
        float inv = __ldg(&g_invS[(b * HQ + h) * NQ + i]);
        float4 p4 = *(const float4*)(g_p + (b * HQ + h) * NQ + tid * 4);
        float4 o;
        o.x = a4.x ? p4.x * inv : 0.f;
        o.y = a4.y ? p4.y * inv : 0.f;
        o.z = a4.z ? p4.z * inv : 0.f;
        o.w = a4.w ? p4.w * inv : 0.f;
        *(float4*)(alpha + (((size_t)(b * HQ + h) * NQ + i)) * NQ + tid * 4) = o;
    }
}

// ---------------- launch ----------------
extern "C" void kernel_launch(void* const* d_in, const int* in_sizes, int n_in,
                              void* d_out, int out_size) {
    const float* x   = (const float*)d_in[0];  // node_feats (8,1024,25)
    const int*   adj = (const int*)d_in[1];    // adj (8,1024,1024)
    const float* W   = (const float*)d_in[2];  // W (8,25,16)
    const float* a   = (const float*)d_in[3];  // a (8,32,1)

    float* out1  = (float*)d_out;                       // relu(h_prime)
    float* alpha = (float*)d_out + (size_t)BQ * NQ * HD; // alpha

    k1_prep<<<64, 256>>>(x, W, a);
    k2_gemm<<<128, 288>>>(adj, out1);
    k3_alpha<<<8192, 256>>>(adj, alpha);
}

// round 6
// speedup vs baseline: 1.1478x; 1.1478x over previous
#include <cuda_runtime.h>

// GAT layer:  B=8, N=1024, F_IN=25, H=8, D=16
// out = [ relu(h_prime) : 8*1024*128 floats | alpha : 8*8*1024*1024 floats ]
//
//   alpha[b,h,i,j] = adj[i,j]*p[h,j] / S[h,i],  p[j]=exp(ej[j]-max_j ej)
//   S[h,i] = sum_j adj[i,j]*p[h,j]                (computed in k3, which
//                                                  already streams adj rows)
//   h_prime[i,:]  = invS * (A @ Y),  Y[j, h*16+d] = p[h,j]*Wh[h,j,d]
//
// Pipeline: k1a (Wh, ej, block max) -> k1b (p, Y=p*Wh) -> k3 (S + alpha)
//           -> k2 (128-col 0/1 GEMM + relu/invS epilogue)

#define BQ 8
#define NQ 1024
#define FQ 25
#define HQ 8
#define DQ 16
#define HD 128

__device__ float g_Y[BQ * NQ * HD];      // [b][j][h*16+d] : p*Wh
__device__ float g_p[BQ * HQ * NQ];      // [b][h][j]
__device__ float g_ej[BQ * HQ * NQ];     // [b][h][j]
__device__ float g_invS[BQ * HQ * NQ];   // [b][h][i]
__device__ float g_bmax[BQ * HQ * 4];    // per-chunk ej max

// ---------------- packed f32x2 helpers ----------------
__device__ __forceinline__ unsigned long long pack2(float lo, float hi) {
    unsigned long long r;
    asm("mov.b64 %0, {%1, %2};" : "=l"(r) : "f"(lo), "f"(hi));
    return r;
}
__device__ __forceinline__ void fma2(unsigned long long& d,
                                     unsigned long long a,
                                     unsigned long long b) {
    asm("fma.rn.f32x2 %0, %1, %2, %0;" : "+l"(d) : "l"(a), "l"(b));
}
__device__ __forceinline__ float2 unpack2(unsigned long long v) {
    float2 f;
    asm("mov.b64 {%0, %1}, %2;" : "=f"(f.x), "=f"(f.y) : "l"(v));
    return f;
}

// ---------------- K1a: Wh, ej, per-chunk max ----------------
// grid = B*H*4 = 256 blocks, 256 threads, thread = one node j.
__global__ __launch_bounds__(256) void k1a(const float* __restrict__ x,
                                           const float* __restrict__ W,
                                           const float* __restrict__ a) {
    int bh = blockIdx.x >> 2, chunk = blockIdx.x & 3;
    int b = bh >> 3, h = bh & 7;
    int tid = threadIdx.x;
    __shared__ float Ws[FQ * DQ];
    __shared__ float as[DQ];
    __shared__ float red[8];

    for (int i = tid; i < FQ * DQ; i += 256) Ws[i] = W[h * FQ * DQ + i];
    if (tid < DQ) as[tid] = a[h * 2 * DQ + DQ + tid];
    __syncthreads();

    int j = chunk * 256 + tid;
    const float* xr = x + ((size_t)(b * NQ + j)) * FQ;
    float xf[FQ];
#pragma unroll
    for (int f = 0; f < FQ; f++) xf[f] = xr[f];

    float wh[DQ];
#pragma unroll
    for (int d = 0; d < DQ; d++) {
        float s = 0.f;
#pragma unroll
        for (int f = 0; f < FQ; f++) s += xf[f] * Ws[f * DQ + d];
        wh[d] = s;
    }
    float e = 0.f;
#pragma unroll
    for (int d = 0; d < DQ; d++) e += wh[d] * as[d];

    float* yr = g_Y + ((size_t)(b * NQ + j)) * HD + h * DQ;
#pragma unroll
    for (int q = 0; q < 4; q++)
        *(float4*)(yr + q * 4) = make_float4(wh[q * 4], wh[q * 4 + 1],
                                             wh[q * 4 + 2], wh[q * 4 + 3]);
    g_ej[bh * NQ + j] = e;

    float m = e;
#pragma unroll
    for (int o = 16; o; o >>= 1) m = fmaxf(m, __shfl_xor_sync(0xffffffffu, m, o));
    if ((tid & 31) == 0) red[tid >> 5] = m;
    __syncthreads();
    if (tid == 0) {
        float M = red[0];
#pragma unroll
        for (int w = 1; w < 8; w++) M = fmaxf(M, red[w]);
        g_bmax[blockIdx.x] = M;
    }
}

// ---------------- K1b: p = exp(ej - M); Y *= p ----------------
__global__ __launch_bounds__(256) void k1b() {
    int bh = blockIdx.x >> 2, chunk = blockIdx.x & 3;
    int b = bh >> 3, h = bh & 7;
    int tid = threadIdx.x;
    float M = fmaxf(fmaxf(g_bmax[bh * 4], g_bmax[bh * 4 + 1]),
                    fmaxf(g_bmax[bh * 4 + 2], g_bmax[bh * 4 + 3]));
    int j = chunk * 256 + tid;
    float p = expf(g_ej[bh * NQ + j] - M);
    g_p[bh * NQ + j] = p;
    float* yr = g_Y + ((size_t)(b * NQ + j)) * HD + h * DQ;
#pragma unroll
    for (int q = 0; q < 4; q++) {
        float4 v = *(float4*)(yr + q * 4);
        v.x *= p; v.y *= p; v.z *= p; v.w *= p;
        *(float4*)(yr + q * 4) = v;
    }
}

// ---------------- K3: S (row sums) + invS + alpha ----------------
// grid = B*N (8192) blocks, 256 threads; one adj row per block, all 8 heads.
__global__ __launch_bounds__(256) void k3_alpha(const int* __restrict__ adj,
                                                float* __restrict__ alpha) {
    int b = blockIdx.x >> 10;
    int i = blockIdx.x & 1023;
    int tid = threadIdx.x;
    __shared__ float redS[8][8];  // [warp][h]
    __shared__ float sinv[8];

    int4 a4 = *(const int4*)(adj + ((size_t)(b * NQ + i)) * NQ + tid * 4);

    float4 p4[HQ];
    float s[HQ];
#pragma unroll
    for (int h = 0; h < HQ; h++) {
        p4[h] = *(const float4*)(g_p + (b * HQ + h) * NQ + tid * 4);
        s[h] = (a4.x ? p4[h].x : 0.f) + (a4.y ? p4[h].y : 0.f) +
               (a4.z ? p4[h].z : 0.f) + (a4.w ? p4[h].w : 0.f);
    }
#pragma unroll
    for (int h = 0; h < HQ; h++)
#pragma unroll
        for (int o = 16; o; o >>= 1)
            s[h] += __shfl_xor_sync(0xffffffffu, s[h], o);
    if ((tid & 31) == 0)
#pragma unroll
        for (int h = 0; h < HQ; h++) redS[tid >> 5][h] = s[h];
    __syncthreads();
    if (tid < 8) {
        float t = 0.f;
#pragma unroll
        for (int w = 0; w < 8; w++) t += redS[w][tid];
        float inv = 1.0f / t;
        sinv[tid] = inv;
        g_invS[(b * HQ + tid) * NQ + i] = inv;
    }
    __syncthreads();

#pragma unroll
    for (int h = 0; h < HQ; h++) {
        float inv = sinv[h];
        float4 o;
        o.x = a4.x ? p4[h].x * inv : 0.f;
        o.y = a4.y ? p4[h].y * inv : 0.f;
        o.z = a4.z ? p4[h].z * inv : 0.f;
        o.w = a4.w ? p4[h].w * inv : 0.f;
        *(float4*)(alpha + (((size_t)(b * HQ + h) * NQ + i)) * NQ + tid * 4) = o;
    }
}

// ---------------- K2: C[1024x128] = A @ Y, relu(C*invS) --------
// grid = B * (N/32) = 256 blocks, 256 threads.
// thread: rg = tid>>4 (16 groups x 2 rows), cg = tid&15 (16 groups x 8 cols).
__global__ __launch_bounds__(256) void k2_gemm(const int* __restrict__ adj,
                                               float* __restrict__ out1) {
    int b  = blockIdx.x >> 5;
    int i0 = (blockIdx.x & 31) * 32;

    __shared__ __align__(16) unsigned long long adjP[32 * 32];  // [row][k], 8KB
    __shared__ __align__(16) float Ys[32 * HD];                 // 16KB

    int tid = threadIdx.x;
    int rg = tid >> 4, cg = tid & 15;
    int r0 = rg * 2, c0 = cg * 8;

    unsigned long long acc[2][4];
#pragma unroll
    for (int r = 0; r < 2; r++)
#pragma unroll
        for (int q = 0; q < 4; q++) acc[r][q] = 0ULL;

    for (int kt = 0; kt < 32; kt++) {
        int j0 = kt * 32;
        // adj tile: 32 rows x 32 k, one int4 per thread -> packed dup pairs
        {
            int row = tid >> 3, c4 = tid & 7;
            int4 v = *(const int4*)(adj + ((size_t)(b * NQ + i0 + row)) * NQ + j0 + c4 * 4);
            unsigned long long* dst = adjP + row * 32 + c4 * 4;
            dst[0] = pack2((float)v.x, (float)v.x);
            dst[1] = pack2((float)v.y, (float)v.y);
            dst[2] = pack2((float)v.z, (float)v.z);
            dst[3] = pack2((float)v.w, (float)v.w);
        }
        // Y tile: 32 rows x 128 cols = 1024 float4, 4 per thread
#pragma unroll
        for (int t = 0; t < 4; t++) {
            int idx = tid + t * 256;
            int row = idx >> 5, c4 = idx & 31;
            *(float4*)(Ys + row * HD + c4 * 4) =
                *(const float4*)(g_Y + ((size_t)(b * NQ + j0 + row)) * HD + c4 * 4);
        }
        __syncthreads();

#pragma unroll
        for (int k = 0; k < 32; k++) {
            const ulonglong2* yp = (const ulonglong2*)(Ys + k * HD + c0);
            ulonglong2 u0 = yp[0];
            ulonglong2 u1 = yp[1];
            unsigned long long a0 = adjP[(r0 + 0) * 32 + k];
            unsigned long long a1 = adjP[(r0 + 1) * 32 + k];
            fma2(acc[0][0], a0, u0.x);
            fma2(acc[0][1], a0, u0.y);
            fma2(acc[0][2], a0, u1.x);
            fma2(acc[0][3], a0, u1.y);
            fma2(acc[1][0], a1, u0.x);
            fma2(acc[1][1], a1, u0.y);
            fma2(acc[1][2], a1, u1.x);
            fma2(acc[1][3], a1, u1.y);
        }
        __syncthreads();
    }

    int h = c0 >> 4;
#pragma unroll
    for (int r = 0; r < 2; r++) {
        int i = i0 + r0 + r;
        float inv = __ldg(&g_invS[(b * HQ + h) * NQ + i]);
        float o[8];
#pragma unroll
        for (int q = 0; q < 4; q++) {
            float2 f = unpack2(acc[r][q]);
            o[2 * q]     = fmaxf(f.x * inv, 0.f);
            o[2 * q + 1] = fmaxf(f.y * inv, 0.f);
        }
        float* op = out1 + ((size_t)(b * NQ + i)) * HD + c0;
        *(float4*)(op)     = make_float4(o[0], o[1], o[2], o[3]);
        *(float4*)(op + 4) = make_float4(o[4], o[5], o[6], o[7]);
    }
}

// ---------------- launch ----------------
extern "C" void kernel_launch(void* const* d_in, const int* in_sizes, int n_in,
                              void* d_out, int out_size) {
    const float* x   = (const float*)d_in[0];  // node_feats (8,1024,25)
    const int*   adj = (const int*)d_in[1];    // adj (8,1024,1024)
    const float* W   = (const float*)d_in[2];  // W (8,25,16)
    const float* a   = (const float*)d_in[3];  // a (8,32,1)

    float* out1  = (float*)d_out;                        // relu(h_prime)
    float* alpha = (float*)d_out + (size_t)BQ * NQ * HD; // alpha

    k1a<<<256, 256>>>(x, W, a);
    k1b<<<256, 256>>>();
    k3_alpha<<<8192, 256>>>(adj, alpha);
    k2_gemm<<<256, 256>>>(adj, out1);
}

// round 9
// speedup vs baseline: 2.8615x; 2.4931x over previous
#include <cuda_runtime.h>
#include <cuda_bf16.h>
#include <cstdint>

// GAT layer:  B=8, N=1024, F_IN=25, H=8, D=16
// out = [ relu(h_prime) : 8*1024*128 floats | alpha : 8*8*1024*1024 floats ]
//
//   alpha[b,h,i,j] = adj[i,j]*p[h,j] / S[h,i],  p[j]=exp(ej[j]-max_j ej)
//   S[h,i] computed in k3 (streams adj anyway; also emits adj as bf16)
//   h_prime = invS * (A @ Y),  Y[j, h*16+d] = p[h,j]*Wh[h,j,d]
//
// k2: warp-level HMMA (mma.sync m16n8k16 bf16 — target-portable, no sm_103a
// PTX needed) with bf16 split:  C = A@Yhi + A@Ylo, fp32 accumulators.

#define BQ 8
#define NQ 1024
#define FQ 25
#define HQ 8
#define DQ 16
#define HD 128

__device__ float g_Y[BQ * NQ * HD];      // [b][j][h*16+d] : Wh (unscaled)
__device__ float g_p[BQ * HQ * NQ];      // [b][h][j]
__device__ float g_ej[BQ * HQ * NQ];     // [b][h][j]
__device__ float g_invS[BQ * HQ * NQ];   // [b][h][i]
__device__ float g_bmax[BQ * HQ * 4];    // per-chunk ej max
__device__ __align__(16) __nv_bfloat16 g_Yhi[BQ * HD * NQ];    // [b][c][j]
__device__ __align__(16) __nv_bfloat16 g_Ylo[BQ * HD * NQ];    // [b][c][j]
__device__ __align__(16) __nv_bfloat16 g_adjbf[BQ * NQ * NQ];  // [b][i][j]

// ---------------- PTX helpers ----------------
__device__ __forceinline__ uint32_t smem_u32(const void* p) {
    uint32_t a;
    asm("{ .reg .u64 t; cvta.to.shared.u64 t, %1; cvt.u32.u64 %0, t; }"
        : "=r"(a) : "l"(p));
    return a;
}
#define CP_ASYNC16(saddr, gptr)                                                \
    asm volatile("cp.async.cg.shared.global [%0], [%1], 16;"                   \
                 :: "r"(saddr), "l"(gptr) : "memory")
#define CP_COMMIT() asm volatile("cp.async.commit_group;" ::: "memory")
#define CP_WAIT1()  asm volatile("cp.async.wait_group 1;" ::: "memory")
#define LDSM4(r0, r1, r2, r3, addr)                                            \
    asm volatile("ldmatrix.sync.aligned.m8n8.x4.shared.b16 {%0,%1,%2,%3}, [%4];" \
                 : "=r"(r0), "=r"(r1), "=r"(r2), "=r"(r3) : "r"(addr))
#define MMA16816(c, a, b0, b1)                                                 \
    asm volatile("mma.sync.aligned.m16n8k16.row.col.f32.bf16.bf16.f32 "        \
                 "{%0,%1,%2,%3}, {%4,%5,%6,%7}, {%8,%9}, {%0,%1,%2,%3};"       \
                 : "+f"((c)[0]), "+f"((c)[1]), "+f"((c)[2]), "+f"((c)[3])      \
                 : "r"((a)[0]), "r"((a)[1]), "r"((a)[2]), "r"((a)[3]),         \
                   "r"(b0), "r"(b1))

// ---------------- K1a: Wh, ej, per-chunk max ----------------
__global__ __launch_bounds__(256) void k1a(const float* __restrict__ x,
                                           const float* __restrict__ W,
                                           const float* __restrict__ a) {
    int bh = blockIdx.x >> 2, chunk = blockIdx.x & 3;
    int b = bh >> 3, h = bh & 7;
    int tid = threadIdx.x;
    __shared__ float Ws[FQ * DQ];
    __shared__ float as[DQ];
    __shared__ float red[8];

    for (int i = tid; i < FQ * DQ; i += 256) Ws[i] = W[h * FQ * DQ + i];
    if (tid < DQ) as[tid] = a[h * 2 * DQ + DQ + tid];
    __syncthreads();

    int j = chunk * 256 + tid;
    const float* xr = x + ((size_t)(b * NQ + j)) * FQ;
    float xf[FQ];
#pragma unroll
    for (int f = 0; f < FQ; f++) xf[f] = xr[f];

    float wh[DQ];
#pragma unroll
    for (int d = 0; d < DQ; d++) {
        float s = 0.f;
#pragma unroll
        for (int f = 0; f < FQ; f++) s += xf[f] * Ws[f * DQ + d];
        wh[d] = s;
    }
    float e = 0.f;
#pragma unroll
    for (int d = 0; d < DQ; d++) e += wh[d] * as[d];

    float* yr = g_Y + ((size_t)(b * NQ + j)) * HD + h * DQ;
#pragma unroll
    for (int q = 0; q < 4; q++)
        *(float4*)(yr + q * 4) = make_float4(wh[q * 4], wh[q * 4 + 1],
                                             wh[q * 4 + 2], wh[q * 4 + 3]);
    g_ej[bh * NQ + j] = e;

    float m = e;
#pragma unroll
    for (int o = 16; o; o >>= 1) m = fmaxf(m, __shfl_xor_sync(0xffffffffu, m, o));
    if ((tid & 31) == 0) red[tid >> 5] = m;
    __syncthreads();
    if (tid == 0) {
        float M = red[0];
#pragma unroll
        for (int w = 1; w < 8; w++) M = fmaxf(M, red[w]);
        g_bmax[blockIdx.x] = M;
    }
}

// ---------------- K1b: p; Yt_hi/Yt_lo (bf16 split, transposed) ----------
__global__ __launch_bounds__(256) void k1b() {
    int bh = blockIdx.x >> 2, chunk = blockIdx.x & 3;
    int b = bh >> 3, h = bh & 7;
    int tid = threadIdx.x;
    float M = fmaxf(fmaxf(g_bmax[bh * 4], g_bmax[bh * 4 + 1]),
                    fmaxf(g_bmax[bh * 4 + 2], g_bmax[bh * 4 + 3]));
    int j = chunk * 256 + tid;
    float p = expf(g_ej[bh * NQ + j] - M);
    g_p[bh * NQ + j] = p;
    const float* yr = g_Y + ((size_t)(b * NQ + j)) * HD + h * DQ;
#pragma unroll
    for (int d = 0; d < DQ; d++) {
        float yv = yr[d] * p;
        __nv_bfloat16 hi = __float2bfloat16(yv);
        __nv_bfloat16 lo = __float2bfloat16(yv - __bfloat162float(hi));
        size_t o = ((size_t)(b * HD + h * DQ + d)) * NQ + j;
        g_Yhi[o] = hi;
        g_Ylo[o] = lo;
    }
}

// ---------------- K3: S + invS + alpha + adj->bf16 ----------------
__global__ __launch_bounds__(256) void k3_alpha(const int* __restrict__ adj,
                                                float* __restrict__ alpha) {
    int b = blockIdx.x >> 10;
    int i = blockIdx.x & 1023;
    int tid = threadIdx.x;
    __shared__ float redS[8][8];
    __shared__ float sinv[8];

    int4 a4 = *(const int4*)(adj + ((size_t)(b * NQ + i)) * NQ + tid * 4);

    // emit bf16 adjacency row for k2's tensor-core GEMM
    {
        uint2 w;
        w.x = (a4.x ? 0x3F80u : 0u) | ((a4.y ? 0x3F80u : 0u) << 16);
        w.y = (a4.z ? 0x3F80u : 0u) | ((a4.w ? 0x3F80u : 0u) << 16);
        *(uint2*)(g_adjbf + ((size_t)(b * NQ + i)) * NQ + tid * 4) = w;
    }

    float4 p4[HQ];
    float s[HQ];
#pragma unroll
    for (int h = 0; h < HQ; h++) {
        p4[h] = *(const float4*)(g_p + (b * HQ + h) * NQ + tid * 4);
        s[h] = (a4.x ? p4[h].x : 0.f) + (a4.y ? p4[h].y : 0.f) +
               (a4.z ? p4[h].z : 0.f) + (a4.w ? p4[h].w : 0.f);
    }
#pragma unroll
    for (int h = 0; h < HQ; h++)
#pragma unroll
        for (int o = 16; o; o >>= 1)
            s[h] += __shfl_xor_sync(0xffffffffu, s[h], o);
    if ((tid & 31) == 0)
#pragma unroll
        for (int h = 0; h < HQ; h++) redS[tid >> 5][h] = s[h];
    __syncthreads();
    if (tid < 8) {
        float t = 0.f;
#pragma unroll
        for (int w = 0; w < 8; w++) t += redS[w][tid];
        float inv = 1.0f / t;
        sinv[tid] = inv;
        g_invS[(b * HQ + tid) * NQ + i] = inv;
    }
    __syncthreads();

#pragma unroll
    for (int h = 0; h < HQ; h++) {
        float inv = sinv[h];
        float4 o;
        o.x = a4.x ? p4[h].x * inv : 0.f;
        o.y = a4.y ? p4[h].y * inv : 0.f;
        o.z = a4.z ? p4[h].z * inv : 0.f;
        o.w = a4.w ? p4[h].w * inv : 0.f;
        *(float4*)(alpha + (((size_t)(b * HQ + h) * NQ + i)) * NQ + tid * 4) = o;
    }
}

// ---------------- K2: HMMA bf16 split GEMM --------------------------
// grid = B * (N/64) = 128 CTAs, 256 threads (8 warps: 2 m-groups x 4 n-groups).
// CTA tile: C[64,128] = A[64,1024] @ Yt^T; K-loop 16 tiles of 64.
// smem per stage: A 64x(72)bf16 = 9216B, Bh 128x72 = 18432B, Bl 18432B.
// 2 stages, cp.async 2-deep pipeline. Row stride 144B -> conflict-free ldmatrix.
#define K2_STAGE 46080
#define K2_SMEM  (2 * K2_STAGE)

__device__ __forceinline__ void k2_fill(uint32_t sbase, int b, int i0, int j0,
                                        int tid) {
    uint32_t As = sbase, Bh = sbase + 9216, Bl = sbase + 27648;
#pragma unroll
    for (int t = 0; t < 2; t++) {  // A: 512 chunks of 16B
        int idx = tid + t * 256;
        int row = idx >> 3, ch = idx & 7;
        const void* g = g_adjbf + ((size_t)(b * NQ + i0 + row)) * NQ + j0 + ch * 8;
        CP_ASYNC16(As + row * 144 + ch * 16, g);
    }
#pragma unroll
    for (int t = 0; t < 4; t++) {  // Bh/Bl: 1024 chunks each
        int idx = tid + t * 256;
        int row = idx >> 3, ch = idx & 7;
        size_t go = ((size_t)(b * HD + row)) * NQ + j0 + ch * 8;
        CP_ASYNC16(Bh + row * 144 + ch * 16, (const void*)(g_Yhi + go));
        CP_ASYNC16(Bl + row * 144 + ch * 16, (const void*)(g_Ylo + go));
    }
}

__global__ __launch_bounds__(256) void k2_mma(float* __restrict__ out1) {
    extern __shared__ char smem_raw[];
    uint32_t sb = smem_u32(smem_raw);

    int tid = threadIdx.x, wid = tid >> 5, lid = tid & 31;
    int b = blockIdx.x >> 4;
    int i0 = (blockIdx.x & 15) * 64;
    int wm = wid & 1, wn = wid >> 1;  // warp tile: M32 x N32

    float acc[2][4][4];
#pragma unroll
    for (int f = 0; f < 2; f++)
#pragma unroll
        for (int j = 0; j < 4; j++)
#pragma unroll
            for (int q = 0; q < 4; q++) acc[f][j][q] = 0.f;

    // lane address components
    int la  = (lid & 7) + ((lid >> 3) & 1) * 8;  // A: row within m16
    int lk  = (lid >> 4) * 8;                    // A: k half
    int lnr = (lid & 7) + (lid >> 4) * 8;        // B: n row within n16
    int lbk = ((lid >> 3) & 1) * 8;              // B: k half

    k2_fill(sb, b, i0, 0, tid);
    CP_COMMIT();
    k2_fill(sb + K2_STAGE, b, i0, 64, tid);
    CP_COMMIT();

    for (int kt = 0; kt < 16; kt++) {
        uint32_t As = sb + (kt & 1) * K2_STAGE;
        uint32_t Bhs = As + 9216, Bls = As + 27648;
        CP_WAIT1();
        __syncthreads();

#pragma unroll
        for (int kk = 0; kk < 4; kk++) {
            uint32_t a[2][4], bh[2][4], bl[2][4];
#pragma unroll
            for (int f = 0; f < 2; f++)
                LDSM4(a[f][0], a[f][1], a[f][2], a[f][3],
                      As + (uint32_t)((wm * 32 + f * 16 + la) * 144 +
                                      (kk * 16 + lk) * 2));
#pragma unroll
            for (int g = 0; g < 2; g++) {
                uint32_t ro = (uint32_t)((wn * 32 + g * 16 + lnr) * 144 +
                                         (kk * 16 + lbk) * 2);
                LDSM4(bh[g][0], bh[g][1], bh[g][2], bh[g][3], Bhs + ro);
                LDSM4(bl[g][0], bl[g][1], bl[g][2], bl[g][3], Bls + ro);
            }
#pragma unroll
            for (int f = 0; f < 2; f++)
#pragma unroll
                for (int j = 0; j < 4; j++) {
                    int g = j >> 1, jj = j & 1;
                    MMA16816(acc[f][j], a[f], bh[g][jj * 2], bh[g][jj * 2 + 1]);
                    MMA16816(acc[f][j], a[f], bl[g][jj * 2], bl[g][jj * 2 + 1]);
                }
        }
        __syncthreads();
        if (kt + 2 < 16) k2_fill(sb + (kt & 1) * K2_STAGE, b, i0, (kt + 2) * 64, tid);
        CP_COMMIT();  // always commit so group counting stays uniform
    }

    // epilogue: relu(C * invS) -> out1
#pragma unroll
    for (int f = 0; f < 2; f++) {
        int i_lo = i0 + wm * 32 + f * 16 + (lid >> 2);
        int i_hi = i_lo + 8;
#pragma unroll
        for (int j = 0; j < 4; j++) {
            int cbase = wn * 32 + j * 8;
            int c0 = cbase + (lid & 3) * 2;
            int h = cbase >> 4;
            float invLo = g_invS[(b * HQ + h) * NQ + i_lo];
            float invHi = g_invS[(b * HQ + h) * NQ + i_hi];
            float2 vlo, vhi;
            vlo.x = fmaxf(acc[f][j][0] * invLo, 0.f);
            vlo.y = fmaxf(acc[f][j][1] * invLo, 0.f);
            vhi.x = fmaxf(acc[f][j][2] * invHi, 0.f);
            vhi.y = fmaxf(acc[f][j][3] * invHi, 0.f);
            *(float2*)(out1 + ((size_t)(b * NQ + i_lo)) * HD + c0) = vlo;
            *(float2*)(out1 + ((size_t)(b * NQ + i_hi)) * HD + c0) = vhi;
        }
    }
}

// ---------------- launch ----------------
extern "C" void kernel_launch(void* const* d_in, const int* in_sizes, int n_in,
                              void* d_out, int out_size) {
    const float* x   = (const float*)d_in[0];  // node_feats (8,1024,25)
    const int*   adj = (const int*)d_in[1];    // adj (8,1024,1024)
    const float* W   = (const float*)d_in[2];  // W (8,25,16)
    const float* a   = (const float*)d_in[3];  // a (8,32,1)

    float* out1  = (float*)d_out;                        // relu(h_prime)
    float* alpha = (float*)d_out + (size_t)BQ * NQ * HD; // alpha

    static int smem_set = 0;
    if (!smem_set) {
        cudaFuncSetAttribute(k2_mma, cudaFuncAttributeMaxDynamicSharedMemorySize,
                             K2_SMEM);
        smem_set = 1;
    }

    k1a<<<256, 256>>>(x, W, a);
    k1b<<<256, 256>>>();
    k3_alpha<<<8192, 256>>>(adj, alpha);
    k2_mma<<<128, 256, K2_SMEM>>>(out1);
}